// round 11
// baseline (speedup 1.0000x reference)
#include <cuda_runtime.h>
#include <cuda_fp16.h>
#include <stdint.h>

#define N_TOT   131072
#define C_DIM   512
#define H_NUM   8
#define P_NUM   1024
#define C3      1536
#define RPE_MAX 33

static __device__ __half g_qkv [(size_t)N_TOT * C3];     // stage1 out (half)
static __device__ __half g_ao  [(size_t)N_TOT * C_DIM];  // attn out (half)
static __device__ __half g_gath[(size_t)N_TOT * C_DIM];  // feat[order] half
static __device__ __half g_w1  [(size_t)C3 * C_DIM];     // qkv_w half
static __device__ __half g_w3  [(size_t)C_DIM * C_DIM];  // proj_w half

// ---------------------------------------------------------------- helpers --
__device__ __forceinline__ uint32_t sptr(const void* p) {
    return (uint32_t)__cvta_generic_to_shared(p);
}
__device__ __forceinline__ void ldsm_x4(uint32_t& r0, uint32_t& r1,
                                        uint32_t& r2, uint32_t& r3, uint32_t addr) {
    asm volatile("ldmatrix.sync.aligned.m8n8.x4.shared.b16 {%0,%1,%2,%3}, [%4];"
                 : "=r"(r0), "=r"(r1), "=r"(r2), "=r"(r3) : "r"(addr));
}
__device__ __forceinline__ void mma_f16(float* d,
                                        uint32_t a0, uint32_t a1, uint32_t a2, uint32_t a3,
                                        uint32_t b0, uint32_t b1)
{
    asm volatile(
        "mma.sync.aligned.m16n8k16.row.col.f32.f16.f16.f32 "
        "{%0,%1,%2,%3}, {%4,%5,%6,%7}, {%8,%9}, {%0,%1,%2,%3};"
        : "+f"(d[0]), "+f"(d[1]), "+f"(d[2]), "+f"(d[3])
        : "r"(a0), "r"(a1), "r"(a2), "r"(a3), "r"(b0), "r"(b1));
}
__device__ __forceinline__ uint32_t pkh2(float lo, float hi) {
    __half2 h = __floats2half2_rn(lo, hi);
    return *(uint32_t*)&h;
}
__device__ __forceinline__ void cpa16(uint32_t dst, const void* src) {
    asm volatile("cp.async.cg.shared.global [%0], [%1], 16;"
                 :: "r"(dst), "l"(src) : "memory");
}
__device__ __forceinline__ void cpa_commit() {
    asm volatile("cp.async.commit_group;" ::: "memory");
}
__device__ __forceinline__ void cpa_wait1() {
    asm volatile("cp.async.wait_group 1;" ::: "memory");
}

// ---------------------------------------------------------------------------
// Pre-pass: gather + fp32->fp16 (feat[order] -> g_gath); weight cvt to fp16
// ---------------------------------------------------------------------------
__global__ __launch_bounds__(256) void gather_cvt(
    const float* __restrict__ feat, const int* __restrict__ order,
    __half* __restrict__ outb)
{
    size_t idx = (size_t)blockIdx.x * 256 + threadIdx.x;  // 8 floats each
    int m = (int)(idx >> 6);
    int c = (int)(idx & 63) << 3;
    int src = order[m];
    const float* fp = feat + (size_t)src * C_DIM + c;
    float4 v0 = *(const float4*)(fp);
    float4 v1 = *(const float4*)(fp + 4);
    __half h[8];
    h[0]=__float2half_rn(v0.x); h[1]=__float2half_rn(v0.y);
    h[2]=__float2half_rn(v0.z); h[3]=__float2half_rn(v0.w);
    h[4]=__float2half_rn(v1.x); h[5]=__float2half_rn(v1.y);
    h[6]=__float2half_rn(v1.z); h[7]=__float2half_rn(v1.w);
    *(uint4*)(outb + idx * 8) = *(uint4*)h;
}

__global__ __launch_bounds__(256) void cvt_half(
    const float* __restrict__ in, __half* __restrict__ outb)
{
    size_t idx = (size_t)blockIdx.x * 256 + threadIdx.x;
    const float* fp = in + idx * 8;
    float4 v0 = *(const float4*)(fp);
    float4 v1 = *(const float4*)(fp + 4);
    __half h[8];
    h[0]=__float2half_rn(v0.x); h[1]=__float2half_rn(v0.y);
    h[2]=__float2half_rn(v0.z); h[3]=__float2half_rn(v0.w);
    h[4]=__float2half_rn(v1.x); h[5]=__float2half_rn(v1.y);
    h[6]=__float2half_rn(v1.z); h[7]=__float2half_rn(v1.w);
    *(uint4*)(outb + idx * 8) = *(uint4*)h;
}

// ---------------------------------------------------------------------------
// FP16 mma.sync GEMM (NT), fp32 accum: out = A * W^T + bias.
// Block 128m x 128n, BK=64, 256 threads: 8 warps (2m x 4n) of 64x32 tiles.
// 3-stage cp.async pipeline; 2 CTAs/SM (independent barriers -> desynced
// LDSM bursts fill each other's tensor-pipe bubbles).
// ---------------------------------------------------------------------------
#define ROWB     144                      // 128B data + 16B pad per row
#define A_BYTES  (128 * ROWB)             // 18432
#define B_BYTES  (128 * ROWB)             // 18432
#define STG      (A_BYTES + B_BYTES)      // 36864
#define NSTAGE   3
#define DYN_SMEM (NSTAGE * STG)           // 110592 (x2 CTAs = 216 KB)

template<int OUT_HALF>
__global__ __launch_bounds__(256, 2) void gemm_h(
    const __half* __restrict__ A, const __half* __restrict__ W,
    const float* __restrict__ bias, void* __restrict__ outv,
    const int* __restrict__ sidx, int Ncols, int Kd)
{
    extern __shared__ char dyn[];
    const uint32_t sbase = sptr(dyn);

    const int t = threadIdx.x;
    const int warp = t >> 5;
    const int lane = t & 31;
    const int wm = warp & 1;        // 2 warps over M (64 rows each)
    const int wn = warp >> 1;       // 4 warps over N (32 cols each)
    const int m0 = blockIdx.y * 128;
    const int j0 = blockIdx.x * 128;

    // Fill: thread covers 4 x 16B chunks of A row fr and B row fr.
    const int fr = t >> 1;          // 0..127
    const int cb = (t & 1) * 64;    // byte offset 0 or 64 within the 128B row
    const __half* Ag = A + (size_t)(m0 + fr) * Kd + cb / 2;
    const __half* Wg = W + (size_t)(j0 + fr) * Kd + cb / 2;
    const uint32_t soA = fr * ROWB + cb;

#define ISSUE_STAGE(s, kt) do {                                   \
        uint32_t ab_ = sbase + (s) * STG + soA;                   \
        uint32_t bb_ = ab_ + A_BYTES;                             \
        const __half* ag_ = Ag + (kt) * 64;                       \
        const __half* wg_ = Wg + (kt) * 64;                       \
        cpa16(ab_,      ag_);                                     \
        cpa16(ab_ + 16, ag_ + 8);                                 \
        cpa16(ab_ + 32, ag_ + 16);                                \
        cpa16(ab_ + 48, ag_ + 24);                                \
        cpa16(bb_,      wg_);                                     \
        cpa16(bb_ + 16, wg_ + 8);                                 \
        cpa16(bb_ + 32, wg_ + 16);                                \
        cpa16(bb_ + 48, wg_ + 24);                                \
    } while (0)

    float acc[4][4][4];
    #pragma unroll
    for (int mt = 0; mt < 4; mt++)
        #pragma unroll
        for (int nt = 0; nt < 4; nt++)
            #pragma unroll
            for (int i = 0; i < 4; i++) acc[mt][nt][i] = 0.f;

    const int iters = Kd >> 6;   // 8 for Kd=512

    ISSUE_STAGE(0, 0); cpa_commit();
    ISSUE_STAGE(1, 1); cpa_commit();

    const int a_roff = (lane & 7) + ((lane & 8) ? 8 : 0);
    const int a_cB   = (lane & 16) ? 16 : 0;
    const int b_roff = (lane & 7) + ((lane & 16) ? 8 : 0);
    const int b_cB   = (lane & 8) ? 16 : 0;

    for (int c = 0; c < iters; c++) {
        const int s = c % NSTAGE;
        cpa_wait1();
        __syncthreads();
        if (c + 2 < iters) ISSUE_STAGE((c + 2) % NSTAGE, c + 2);
        cpa_commit();

        const uint32_t ab = sbase + s * STG;
        const uint32_t bb = ab + A_BYTES;
        #pragma unroll
        for (int ks = 0; ks < 4; ks++) {            // 4 k16 steps within BK=64
            uint32_t bf[4][2];
            #pragma unroll
            for (int ntp = 0; ntp < 2; ntp++) {
                ldsm_x4(bf[2*ntp][0], bf[2*ntp][1], bf[2*ntp+1][0], bf[2*ntp+1][1],
                        bb + (wn * 32 + ntp * 16 + b_roff) * ROWB + ks * 32 + b_cB);
            }
            #pragma unroll
            for (int mt = 0; mt < 4; mt++) {
                uint32_t a0, a1, a2, a3;
                ldsm_x4(a0, a1, a2, a3,
                        ab + (wm * 64 + mt * 16 + a_roff) * ROWB + ks * 32 + a_cB);
                #pragma unroll
                for (int nt = 0; nt < 4; nt++)
                    mma_f16(acc[mt][nt], a0, a1, a2, a3, bf[nt][0], bf[nt][1]);
            }
        }
    }
    __syncthreads();

    const int gr = lane >> 2;
    const int gc = lane & 3;
    #pragma unroll
    for (int mt = 0; mt < 4; mt++) {
        int m_a = m0 + wm * 64 + mt * 16 + gr;
        int m_b = m_a + 8;
        int orow_a = sidx ? sidx[m_a] : m_a;
        int orow_b = sidx ? sidx[m_b] : m_b;
        #pragma unroll
        for (int nt = 0; nt < 4; nt++) {
            int col = j0 + wn * 32 + nt * 8 + gc * 2;
            float b0 = bias[col], b1 = bias[col + 1];
            if (OUT_HALF) {
                __half* out = (__half*)outv;
                *(__half2*)(out + (size_t)orow_a * Ncols + col) =
                    __floats2half2_rn(acc[mt][nt][0] + b0, acc[mt][nt][1] + b1);
                *(__half2*)(out + (size_t)orow_b * Ncols + col) =
                    __floats2half2_rn(acc[mt][nt][2] + b0, acc[mt][nt][3] + b1);
            } else {
                float* out = (float*)outv;
                *(float2*)(out + (size_t)orow_a * Ncols + col) =
                    make_float2(acc[mt][nt][0] + b0, acc[mt][nt][1] + b1);
                *(float2*)(out + (size_t)orow_b * Ncols + col) =
                    make_float2(acc[mt][nt][2] + b0, acc[mt][nt][3] + b1);
            }
        }
    }
#undef ISSUE_STAGE
}

// ---------------------------------------------------------------------------
// Attention (fp16 MMA, fp32 softmax): one block per (patch, head), 8 warps.
// Register softmax; PV A-fragments packed directly from C-fragments.
// ---------------------------------------------------------------------------
#define QS0 0                      // 128 rows x 144B (64 halves + 8 pad)
#define KS0 18432
#define VT0 36864                  // 64 rows x 272B (128 halves + 8 pad)
#define CX0 54272
#define CY0 54784
#define CZ0 55296
#define RP0 55808                  // 3 x RPE_MAX floats
#define ATTN_SMEM 56320

__global__ __launch_bounds__(256, 2) void attn_kernel(
    const __half* __restrict__ qkv, const int* __restrict__ gcoord,
    const int* __restrict__ order, const float* __restrict__ rpe,
    __half* __restrict__ out, int rpe_num, int pos_b)
{
    extern __shared__ char sm[];
    const int p = blockIdx.x;
    const int h = blockIdx.y;
    const int t = threadIdx.x;
    const int lane = t & 31;
    const int warp = t >> 5;

    int* cx = (int*)(sm + CX0);
    int* cy = (int*)(sm + CY0);
    int* cz = (int*)(sm + CZ0);
    float* rp = (float*)(sm + RP0);

    for (int f = t; f < 1024; f += 256) {
        int i  = f >> 3;
        int hg = (f & 7) * 8;
        const __half* base = qkv + (size_t)(p * 128 + i) * C3 + h * 64 + hg;
        uint4 qv = *(const uint4*)(base);
        uint4 kv = *(const uint4*)(base + 512);
        uint4 vv = *(const uint4*)(base + 1024);
        *(uint4*)(sm + QS0 + i * 144 + hg * 2) = qv;
        *(uint4*)(sm + KS0 + i * 144 + hg * 2) = kv;
        const __half* vh = (const __half*)&vv;
        #pragma unroll
        for (int j = 0; j < 8; j++)
            *(__half*)(sm + VT0 + (hg + j) * 272 + i * 2) = vh[j];
    }
    if (t < 128) {
        int gi = order[p * 128 + t];
        cx[t] = gcoord[gi * 3 + 0];
        cy[t] = gcoord[gi * 3 + 1];
        cz[t] = gcoord[gi * 3 + 2];
    }
    if (t < 3 * rpe_num) {
        rp[(t / rpe_num) * RPE_MAX + (t % rpe_num)] = rpe[t * H_NUM + h];
    }
    __syncthreads();

    const int m0w = warp * 16;
    const int a_roff = (lane & 7) + ((lane & 8) ? 8 : 0);
    const int a_cB   = (lane & 16) ? 16 : 0;
    const int b_roff = (lane & 7) + ((lane & 16) ? 8 : 0);
    const int b_cB   = (lane & 8) ? 16 : 0;
    const int gr = lane >> 2;
    const int gc = lane & 3;

    float acc[16][4];
    #pragma unroll
    for (int nt = 0; nt < 16; nt++)
        #pragma unroll
        for (int i = 0; i < 4; i++) acc[nt][i] = 0.f;

    #pragma unroll
    for (int d0 = 0; d0 < 64; d0 += 16) {
        uint32_t a0, a1, a2, a3;
        ldsm_x4(a0, a1, a2, a3,
                sptr(sm + QS0 + (m0w + a_roff) * 144 + d0 * 2 + a_cB));
        #pragma unroll
        for (int ntp = 0; ntp < 8; ntp++) {
            uint32_t b0, b1, c0, c1;
            ldsm_x4(b0, b1, c0, c1,
                    sptr(sm + KS0 + (ntp * 16 + b_roff) * 144 + d0 * 2 + b_cB));
            mma_f16(acc[2*ntp],     a0, a1, a2, a3, b0, b1);
            mma_f16(acc[2*ntp + 1], a0, a1, a2, a3, c0, c1);
        }
    }

    const float scale = 0.125f;
    const int i0 = m0w + gr, i1 = i0 + 8;
    const int x0 = cx[i0], y0 = cy[i0], z0 = cz[i0];
    const int x1 = cx[i1], y1 = cy[i1], z1 = cz[i1];
    #pragma unroll
    for (int nt = 0; nt < 16; nt++) {
        #pragma unroll
        for (int jj = 0; jj < 2; jj++) {
            int j = nt * 8 + gc * 2 + jj;
            int xj = cx[j], yj = cy[j], zj = cz[j];
            int dx0 = min(max(x0 - xj, -pos_b), pos_b) + pos_b;
            int dy0 = min(max(y0 - yj, -pos_b), pos_b) + pos_b;
            int dz0 = min(max(z0 - zj, -pos_b), pos_b) + pos_b;
            int dx1 = min(max(x1 - xj, -pos_b), pos_b) + pos_b;
            int dy1 = min(max(y1 - yj, -pos_b), pos_b) + pos_b;
            int dz1 = min(max(z1 - zj, -pos_b), pos_b) + pos_b;
            acc[nt][jj]     = acc[nt][jj]     * scale
                            + rp[dx0] + rp[RPE_MAX + dy0] + rp[2*RPE_MAX + dz0];
            acc[nt][jj + 2] = acc[nt][jj + 2] * scale
                            + rp[dx1] + rp[RPE_MAX + dy1] + rp[2*RPE_MAX + dz1];
        }
    }

    float mx0 = -1e30f, mx1 = -1e30f;
    #pragma unroll
    for (int nt = 0; nt < 16; nt++) {
        mx0 = fmaxf(mx0, fmaxf(acc[nt][0], acc[nt][1]));
        mx1 = fmaxf(mx1, fmaxf(acc[nt][2], acc[nt][3]));
    }
    mx0 = fmaxf(mx0, __shfl_xor_sync(0xffffffffu, mx0, 1));
    mx0 = fmaxf(mx0, __shfl_xor_sync(0xffffffffu, mx0, 2));
    mx1 = fmaxf(mx1, __shfl_xor_sync(0xffffffffu, mx1, 1));
    mx1 = fmaxf(mx1, __shfl_xor_sync(0xffffffffu, mx1, 2));

    float s0 = 0.f, s1 = 0.f;
    #pragma unroll
    for (int nt = 0; nt < 16; nt++) {
        acc[nt][0] = __expf(acc[nt][0] - mx0);
        acc[nt][1] = __expf(acc[nt][1] - mx0);
        acc[nt][2] = __expf(acc[nt][2] - mx1);
        acc[nt][3] = __expf(acc[nt][3] - mx1);
        s0 += acc[nt][0] + acc[nt][1];
        s1 += acc[nt][2] + acc[nt][3];
    }
    s0 += __shfl_xor_sync(0xffffffffu, s0, 1);
    s0 += __shfl_xor_sync(0xffffffffu, s0, 2);
    s1 += __shfl_xor_sync(0xffffffffu, s1, 1);
    s1 += __shfl_xor_sync(0xffffffffu, s1, 2);

    float o[8][4];
    #pragma unroll
    for (int nt = 0; nt < 8; nt++)
        #pragma unroll
        for (int i = 0; i < 4; i++) o[nt][i] = 0.f;

    #pragma unroll
    for (int kg = 0; kg < 8; kg++) {
        uint32_t a0 = pkh2(acc[2*kg][0],     acc[2*kg][1]);
        uint32_t a1 = pkh2(acc[2*kg][2],     acc[2*kg][3]);
        uint32_t a2 = pkh2(acc[2*kg + 1][0], acc[2*kg + 1][1]);
        uint32_t a3 = pkh2(acc[2*kg + 1][2], acc[2*kg + 1][3]);
        #pragma unroll
        for (int ntp = 0; ntp < 4; ntp++) {
            uint32_t b0, b1, c0, c1;
            ldsm_x4(b0, b1, c0, c1,
                    sptr(sm + VT0 + (ntp * 16 + b_roff) * 272 + kg * 32 + b_cB));
            mma_f16(o[2*ntp],     a0, a1, a2, a3, b0, b1);
            mma_f16(o[2*ntp + 1], a0, a1, a2, a3, c0, c1);
        }
    }

    const float inv0 = 1.f / s0;
    const float inv1 = 1.f / s1;
    #pragma unroll
    for (int nt = 0; nt < 8; nt++) {
        int col = h * 64 + nt * 8 + gc * 2;
        *(__half2*)(out + (size_t)(p * 128 + i0) * C_DIM + col) =
            __floats2half2_rn(o[nt][0] * inv0, o[nt][1] * inv0);
        *(__half2*)(out + (size_t)(p * 128 + i1) * C_DIM + col) =
            __floats2half2_rn(o[nt][2] * inv1, o[nt][3] * inv1);
    }
}

// ---------------------------------------------------------------------------
extern "C" void kernel_launch(void* const* d_in, const int* in_sizes, int n_in,
                              void* d_out, int out_size)
{
    const float* feat   = (const float*)d_in[0];
    const int*   gcoord = (const int*)  d_in[1];
    const int*   order  = (const int*)  d_in[2];
    const float* qkv_w  = (const float*)d_in[4];
    const float* qkv_b  = (const float*)d_in[5];
    const float* proj_w = (const float*)d_in[6];
    const float* proj_b = (const float*)d_in[7];
    const float* rpe    = (const float*)d_in[8];
    float* out = (float*)d_out;

    int rpe_num = in_sizes[8] / (3 * H_NUM);   // 31 (ref comment is wrong)
    if (rpe_num > RPE_MAX) rpe_num = RPE_MAX;
    int pos_b = (rpe_num - 1) / 2;

    __half *qkv_buf = nullptr, *ao_buf = nullptr, *gath = nullptr,
           *w1 = nullptr, *w3 = nullptr;
    cudaGetSymbolAddress((void**)&qkv_buf, g_qkv);
    cudaGetSymbolAddress((void**)&ao_buf,  g_ao);
    cudaGetSymbolAddress((void**)&gath,    g_gath);
    cudaGetSymbolAddress((void**)&w1,      g_w1);
    cudaGetSymbolAddress((void**)&w3,      g_w3);

    cudaFuncSetAttribute(gemm_h<1>,
                         cudaFuncAttributeMaxDynamicSharedMemorySize, DYN_SMEM);
    cudaFuncSetAttribute(gemm_h<0>,
                         cudaFuncAttributeMaxDynamicSharedMemorySize, DYN_SMEM);
    cudaFuncSetAttribute(attn_kernel,
                         cudaFuncAttributeMaxDynamicSharedMemorySize, ATTN_SMEM);

    // Pre-pass: gather+cvt feat, cvt weights (all to fp16)
    gather_cvt<<<(N_TOT * (C_DIM / 8)) / 256, 256>>>(feat, order, gath);
    cvt_half<<<(C3 * C_DIM / 8) / 256, 256>>>(qkv_w, w1);
    cvt_half<<<(C_DIM * C_DIM / 8) / 256, 256>>>(proj_w, w3);

    // Stage 1: QKV projection (fp16 in, half out)
    dim3 g1(C3 / 128, N_TOT / 128);
    gemm_h<1><<<g1, 256, DYN_SMEM>>>(gath, w1, qkv_b, qkv_buf, nullptr,
                                     C3, C_DIM);

    // Stage 2: attention (half in, half out)
    dim3 ga(P_NUM, H_NUM);
    attn_kernel<<<ga, 256, ATTN_SMEM>>>(qkv_buf, gcoord, order, rpe,
                                        ao_buf, rpe_num, pos_b);

    // Stage 3: output projection + scatter (half in, fp32 out)
    dim3 g3(C_DIM / 128, N_TOT / 128);
    gemm_h<0><<<g3, 256, DYN_SMEM>>>(ao_buf, w3, proj_b, out, order,
                                     C_DIM, C_DIM);
}

// round 12
// speedup vs baseline: 1.2093x; 1.2093x over previous
#include <cuda_runtime.h>
#include <cuda_fp16.h>
#include <stdint.h>

#define N_TOT   131072
#define C_DIM   512
#define H_NUM   8
#define P_NUM   1024
#define C3      1536
#define RPE_MAX 33

static __device__ __half g_qkv [(size_t)N_TOT * C3];     // stage1 out (half)
static __device__ __half g_ao  [(size_t)N_TOT * C_DIM];  // attn out (half)
static __device__ __half g_gath[(size_t)N_TOT * C_DIM];  // feat[order] half
static __device__ __half g_w1  [(size_t)C3 * C_DIM];     // qkv_w half
static __device__ __half g_w3  [(size_t)C_DIM * C_DIM];  // proj_w half

// ---------------------------------------------------------------- helpers --
__device__ __forceinline__ uint32_t sptr(const void* p) {
    return (uint32_t)__cvta_generic_to_shared(p);
}
__device__ __forceinline__ void ldsm_x4(uint32_t& r0, uint32_t& r1,
                                        uint32_t& r2, uint32_t& r3, uint32_t addr) {
    asm volatile("ldmatrix.sync.aligned.m8n8.x4.shared.b16 {%0,%1,%2,%3}, [%4];"
                 : "=r"(r0), "=r"(r1), "=r"(r2), "=r"(r3) : "r"(addr));
}
__device__ __forceinline__ void ldsm_x4t(uint32_t& r0, uint32_t& r1,
                                         uint32_t& r2, uint32_t& r3, uint32_t addr) {
    asm volatile("ldmatrix.sync.aligned.m8n8.x4.trans.shared.b16 {%0,%1,%2,%3}, [%4];"
                 : "=r"(r0), "=r"(r1), "=r"(r2), "=r"(r3) : "r"(addr));
}
__device__ __forceinline__ void mma_f16(float* d,
                                        uint32_t a0, uint32_t a1, uint32_t a2, uint32_t a3,
                                        uint32_t b0, uint32_t b1)
{
    asm volatile(
        "mma.sync.aligned.m16n8k16.row.col.f32.f16.f16.f32 "
        "{%0,%1,%2,%3}, {%4,%5,%6,%7}, {%8,%9}, {%0,%1,%2,%3};"
        : "+f"(d[0]), "+f"(d[1]), "+f"(d[2]), "+f"(d[3])
        : "r"(a0), "r"(a1), "r"(a2), "r"(a3), "r"(b0), "r"(b1));
}
__device__ __forceinline__ uint32_t pkh2(float lo, float hi) {
    __half2 h = __floats2half2_rn(lo, hi);
    return *(uint32_t*)&h;
}
__device__ __forceinline__ void cpa16(uint32_t dst, const void* src) {
    asm volatile("cp.async.cg.shared.global [%0], [%1], 16;"
                 :: "r"(dst), "l"(src) : "memory");
}
__device__ __forceinline__ void cpa_commit() {
    asm volatile("cp.async.commit_group;" ::: "memory");
}
__device__ __forceinline__ void cpa_wait1() {
    asm volatile("cp.async.wait_group 1;" ::: "memory");
}
__device__ __forceinline__ void cpa_wait0() {
    asm volatile("cp.async.wait_group 0;" ::: "memory");
}

// ---------------------------------------------------------------------------
// Pre-pass: gather + fp32->fp16 (feat[order] -> g_gath); weight cvt to fp16
// ---------------------------------------------------------------------------
__global__ __launch_bounds__(256) void gather_cvt(
    const float* __restrict__ feat, const int* __restrict__ order,
    __half* __restrict__ outb)
{
    size_t idx = (size_t)blockIdx.x * 256 + threadIdx.x;  // 8 floats each
    int m = (int)(idx >> 6);
    int c = (int)(idx & 63) << 3;
    int src = order[m];
    const float* fp = feat + (size_t)src * C_DIM + c;
    float4 v0 = *(const float4*)(fp);
    float4 v1 = *(const float4*)(fp + 4);
    __half h[8];
    h[0]=__float2half_rn(v0.x); h[1]=__float2half_rn(v0.y);
    h[2]=__float2half_rn(v0.z); h[3]=__float2half_rn(v0.w);
    h[4]=__float2half_rn(v1.x); h[5]=__float2half_rn(v1.y);
    h[6]=__float2half_rn(v1.z); h[7]=__float2half_rn(v1.w);
    *(uint4*)(outb + idx * 8) = *(uint4*)h;
}

__global__ __launch_bounds__(256) void cvt_half(
    const float* __restrict__ in, __half* __restrict__ outb)
{
    size_t idx = (size_t)blockIdx.x * 256 + threadIdx.x;
    const float* fp = in + idx * 8;
    float4 v0 = *(const float4*)(fp);
    float4 v1 = *(const float4*)(fp + 4);
    __half h[8];
    h[0]=__float2half_rn(v0.x); h[1]=__float2half_rn(v0.y);
    h[2]=__float2half_rn(v0.z); h[3]=__float2half_rn(v0.w);
    h[4]=__float2half_rn(v1.x); h[5]=__float2half_rn(v1.y);
    h[6]=__float2half_rn(v1.z); h[7]=__float2half_rn(v1.w);
    *(uint4*)(outb + idx * 8) = *(uint4*)h;
}

// ---------------------------------------------------------------------------
// FP16 mma.sync GEMM (NT), fp32 accum (Round-10 config: best measured).
// Block 256m x 128n, BK=64, 512 threads: 16 warps (4m x 4n) of 64x32.
// 3-stage cp.async pipeline.
// ---------------------------------------------------------------------------
#define ROWB     144                      // 128B data + 16B pad per row
#define A_BYTES  (256 * ROWB)             // 36864
#define B_BYTES  (128 * ROWB)             // 18432
#define STG      (A_BYTES + B_BYTES)      // 55296
#define NSTAGE   3
#define DYN_SMEM (NSTAGE * STG)           // 165888

template<int OUT_HALF>
__global__ __launch_bounds__(512, 1) void gemm_h(
    const __half* __restrict__ A, const __half* __restrict__ W,
    const float* __restrict__ bias, void* __restrict__ outv,
    const int* __restrict__ sidx, int Ncols, int Kd)
{
    extern __shared__ char dyn[];
    const uint32_t sbase = sptr(dyn);

    const int t = threadIdx.x;
    const int warp = t >> 5;
    const int lane = t & 31;
    const int wm = warp & 3;
    const int wn = warp >> 2;
    const int m0 = blockIdx.y * 256;
    const int j0 = blockIdx.x * 128;

    const int fr = t >> 3;          // 0..63
    const int c8 = t & 7;           // 0..7
    const __half* Ag0 = A + (size_t)(m0 + fr)       * Kd + c8 * 8;
    const __half* Ag1 = A + (size_t)(m0 + fr + 64)  * Kd + c8 * 8;
    const __half* Ag2 = A + (size_t)(m0 + fr + 128) * Kd + c8 * 8;
    const __half* Ag3 = A + (size_t)(m0 + fr + 192) * Kd + c8 * 8;
    const __half* Wg0 = W + (size_t)(j0 + fr)       * Kd + c8 * 8;
    const __half* Wg1 = W + (size_t)(j0 + fr + 64)  * Kd + c8 * 8;
    const uint32_t so0 = fr * ROWB + c8 * 16;
    const uint32_t so1 = (fr + 64)  * ROWB + c8 * 16;
    const uint32_t so2 = (fr + 128) * ROWB + c8 * 16;
    const uint32_t so3 = (fr + 192) * ROWB + c8 * 16;

#define ISSUE_STAGE(s, kt) do {                                   \
        uint32_t ab_ = sbase + (s) * STG;                         \
        uint32_t bb_ = ab_ + A_BYTES;                             \
        int ko_ = (kt) * 64;                                      \
        cpa16(ab_ + so0, Ag0 + ko_);                              \
        cpa16(ab_ + so1, Ag1 + ko_);                              \
        cpa16(ab_ + so2, Ag2 + ko_);                              \
        cpa16(ab_ + so3, Ag3 + ko_);                              \
        cpa16(bb_ + so0, Wg0 + ko_);                              \
        cpa16(bb_ + so1, Wg1 + ko_);                              \
    } while (0)

    float acc[4][4][4];
    #pragma unroll
    for (int mt = 0; mt < 4; mt++)
        #pragma unroll
        for (int nt = 0; nt < 4; nt++)
            #pragma unroll
            for (int i = 0; i < 4; i++) acc[mt][nt][i] = 0.f;

    const int iters = Kd >> 6;   // 8 for Kd=512

    ISSUE_STAGE(0, 0); cpa_commit();
    ISSUE_STAGE(1, 1); cpa_commit();

    const int a_roff = (lane & 7) + ((lane & 8) ? 8 : 0);
    const int a_cB   = (lane & 16) ? 16 : 0;
    const int b_roff = (lane & 7) + ((lane & 16) ? 8 : 0);
    const int b_cB   = (lane & 8) ? 16 : 0;

    for (int c = 0; c < iters; c++) {
        const int s = c % NSTAGE;
        cpa_wait1();
        __syncthreads();
        if (c + 2 < iters) ISSUE_STAGE((c + 2) % NSTAGE, c + 2);
        cpa_commit();

        const uint32_t ab = sbase + s * STG;
        const uint32_t bb = ab + A_BYTES;
        #pragma unroll
        for (int ks = 0; ks < 4; ks++) {
            uint32_t bf[4][2];
            #pragma unroll
            for (int ntp = 0; ntp < 2; ntp++) {
                ldsm_x4(bf[2*ntp][0], bf[2*ntp][1], bf[2*ntp+1][0], bf[2*ntp+1][1],
                        bb + (wn * 32 + ntp * 16 + b_roff) * ROWB + ks * 32 + b_cB);
            }
            #pragma unroll
            for (int mt = 0; mt < 4; mt++) {
                uint32_t a0, a1, a2, a3;
                ldsm_x4(a0, a1, a2, a3,
                        ab + (wm * 64 + mt * 16 + a_roff) * ROWB + ks * 32 + a_cB);
                #pragma unroll
                for (int nt = 0; nt < 4; nt++)
                    mma_f16(acc[mt][nt], a0, a1, a2, a3, bf[nt][0], bf[nt][1]);
            }
        }
    }
    __syncthreads();

    const int gr = lane >> 2;
    const int gc = lane & 3;
    #pragma unroll
    for (int mt = 0; mt < 4; mt++) {
        int m_a = m0 + wm * 64 + mt * 16 + gr;
        int m_b = m_a + 8;
        int orow_a = sidx ? sidx[m_a] : m_a;
        int orow_b = sidx ? sidx[m_b] : m_b;
        #pragma unroll
        for (int nt = 0; nt < 4; nt++) {
            int col = j0 + wn * 32 + nt * 8 + gc * 2;
            float b0 = bias[col], b1 = bias[col + 1];
            if (OUT_HALF) {
                __half* out = (__half*)outv;
                *(__half2*)(out + (size_t)orow_a * Ncols + col) =
                    __floats2half2_rn(acc[mt][nt][0] + b0, acc[mt][nt][1] + b1);
                *(__half2*)(out + (size_t)orow_b * Ncols + col) =
                    __floats2half2_rn(acc[mt][nt][2] + b0, acc[mt][nt][3] + b1);
            } else {
                float* out = (float*)outv;
                *(float2*)(out + (size_t)orow_a * Ncols + col) =
                    make_float2(acc[mt][nt][0] + b0, acc[mt][nt][1] + b1);
                *(float2*)(out + (size_t)orow_b * Ncols + col) =
                    make_float2(acc[mt][nt][2] + b0, acc[mt][nt][3] + b1);
            }
        }
    }
#undef ISSUE_STAGE
}

// ---------------------------------------------------------------------------
// Attention (fp16 MMA, fp32 softmax): one block per (patch, head), 8 warps.
// Fill: pure cp.async 16B (q/k/v all row-major, 144B rows).
// PV B-fragments: ldmatrix.x4.trans directly from row-major V.
// ---------------------------------------------------------------------------
#define QS0 0                      // 128 rows x 144B
#define KS0 18432
#define VS0 36864                  // V row-major: 128 rows x 144B
#define CX0 55296
#define CY0 55808
#define CZ0 56320
#define RP0 56832                  // 3 x RPE_MAX floats (396 B)
#define ATTN_SMEM 57344

__global__ __launch_bounds__(256, 2) void attn_kernel(
    const __half* __restrict__ qkv, const int* __restrict__ gcoord,
    const int* __restrict__ order, const float* __restrict__ rpe,
    __half* __restrict__ out, int rpe_num, int pos_b)
{
    extern __shared__ char sm[];
    const uint32_t smb = sptr(sm);
    const int p = blockIdx.x;
    const int h = blockIdx.y;
    const int t = threadIdx.x;
    const int lane = t & 31;
    const int warp = t >> 5;

    int* cx = (int*)(sm + CX0);
    int* cy = (int*)(sm + CY0);
    int* cz = (int*)(sm + CZ0);
    float* rp = (float*)(sm + RP0);

    // ---- fill q/k/v via cp.async (4 rows x 1 chunk each per thread) ----
    #pragma unroll
    for (int ii = 0; ii < 4; ii++) {
        int f  = t + ii * 256;
        int i  = f >> 3;
        int hg = (f & 7) * 8;
        const __half* base = qkv + (size_t)(p * 128 + i) * C3 + h * 64 + hg;
        uint32_t dst = i * 144 + hg * 2;
        cpa16(smb + QS0 + dst, base);
        cpa16(smb + KS0 + dst, base + 512);
        cpa16(smb + VS0 + dst, base + 1024);
    }
    cpa_commit();
    if (t < 128) {
        int gi = order[p * 128 + t];
        cx[t] = gcoord[gi * 3 + 0];
        cy[t] = gcoord[gi * 3 + 1];
        cz[t] = gcoord[gi * 3 + 2];
    }
    if (t < 3 * rpe_num) {
        rp[(t / rpe_num) * RPE_MAX + (t % rpe_num)] = rpe[t * H_NUM + h];
    }
    cpa_wait0();
    __syncthreads();

    const int m0w = warp * 16;
    const int a_roff = (lane & 7) + ((lane & 8) ? 8 : 0);
    const int a_cB   = (lane & 16) ? 16 : 0;
    const int b_roff = (lane & 7) + ((lane & 16) ? 8 : 0);
    const int b_cB   = (lane & 8) ? 16 : 0;
    const int gr = lane >> 2;
    const int gc = lane & 3;

    // ---- QK^T ----
    float acc[16][4];
    #pragma unroll
    for (int nt = 0; nt < 16; nt++)
        #pragma unroll
        for (int i = 0; i < 4; i++) acc[nt][i] = 0.f;

    #pragma unroll
    for (int d0 = 0; d0 < 64; d0 += 16) {
        uint32_t a0, a1, a2, a3;
        ldsm_x4(a0, a1, a2, a3,
                smb + QS0 + (m0w + a_roff) * 144 + d0 * 2 + a_cB);
        #pragma unroll
        for (int ntp = 0; ntp < 8; ntp++) {
            uint32_t b0, b1, c0, c1;
            ldsm_x4(b0, b1, c0, c1,
                    smb + KS0 + (ntp * 16 + b_roff) * 144 + d0 * 2 + b_cB);
            mma_f16(acc[2*ntp],     a0, a1, a2, a3, b0, b1);
            mma_f16(acc[2*ntp + 1], a0, a1, a2, a3, c0, c1);
        }
    }

    // ---- scale + RPE bias ----
    const float scale = 0.125f;
    const int i0 = m0w + gr, i1 = i0 + 8;
    const int x0 = cx[i0], y0 = cy[i0], z0 = cz[i0];
    const int x1 = cx[i1], y1 = cy[i1], z1 = cz[i1];
    #pragma unroll
    for (int nt = 0; nt < 16; nt++) {
        #pragma unroll
        for (int jj = 0; jj < 2; jj++) {
            int j = nt * 8 + gc * 2 + jj;
            int xj = cx[j], yj = cy[j], zj = cz[j];
            int dx0 = min(max(x0 - xj, -pos_b), pos_b) + pos_b;
            int dy0 = min(max(y0 - yj, -pos_b), pos_b) + pos_b;
            int dz0 = min(max(z0 - zj, -pos_b), pos_b) + pos_b;
            int dx1 = min(max(x1 - xj, -pos_b), pos_b) + pos_b;
            int dy1 = min(max(y1 - yj, -pos_b), pos_b) + pos_b;
            int dz1 = min(max(z1 - zj, -pos_b), pos_b) + pos_b;
            acc[nt][jj]     = acc[nt][jj]     * scale
                            + rp[dx0] + rp[RPE_MAX + dy0] + rp[2*RPE_MAX + dz0];
            acc[nt][jj + 2] = acc[nt][jj + 2] * scale
                            + rp[dx1] + rp[RPE_MAX + dy1] + rp[2*RPE_MAX + dz1];
        }
    }

    // ---- register softmax ----
    float mx0 = -1e30f, mx1 = -1e30f;
    #pragma unroll
    for (int nt = 0; nt < 16; nt++) {
        mx0 = fmaxf(mx0, fmaxf(acc[nt][0], acc[nt][1]));
        mx1 = fmaxf(mx1, fmaxf(acc[nt][2], acc[nt][3]));
    }
    mx0 = fmaxf(mx0, __shfl_xor_sync(0xffffffffu, mx0, 1));
    mx0 = fmaxf(mx0, __shfl_xor_sync(0xffffffffu, mx0, 2));
    mx1 = fmaxf(mx1, __shfl_xor_sync(0xffffffffu, mx1, 1));
    mx1 = fmaxf(mx1, __shfl_xor_sync(0xffffffffu, mx1, 2));

    float s0 = 0.f, s1 = 0.f;
    #pragma unroll
    for (int nt = 0; nt < 16; nt++) {
        acc[nt][0] = __expf(acc[nt][0] - mx0);
        acc[nt][1] = __expf(acc[nt][1] - mx0);
        acc[nt][2] = __expf(acc[nt][2] - mx1);
        acc[nt][3] = __expf(acc[nt][3] - mx1);
        s0 += acc[nt][0] + acc[nt][1];
        s1 += acc[nt][2] + acc[nt][3];
    }
    s0 += __shfl_xor_sync(0xffffffffu, s0, 1);
    s0 += __shfl_xor_sync(0xffffffffu, s0, 2);
    s1 += __shfl_xor_sync(0xffffffffu, s1, 1);
    s1 += __shfl_xor_sync(0xffffffffu, s1, 2);

    // ---- PV: A packed from C-fragments; B via ldmatrix.trans on row-major V
    float o[8][4];
    #pragma unroll
    for (int nt = 0; nt < 8; nt++)
        #pragma unroll
        for (int i = 0; i < 4; i++) o[nt][i] = 0.f;

    #pragma unroll
    for (int kg = 0; kg < 8; kg++) {
        uint32_t a0 = pkh2(acc[2*kg][0],     acc[2*kg][1]);
        uint32_t a1 = pkh2(acc[2*kg][2],     acc[2*kg][3]);
        uint32_t a2 = pkh2(acc[2*kg + 1][0], acc[2*kg + 1][1]);
        uint32_t a3 = pkh2(acc[2*kg + 1][2], acc[2*kg + 1][3]);
        #pragma unroll
        for (int ntp = 0; ntp < 4; ntp++) {
            // rows = k (lane&15 pattern via a_roff), cols = n0 (+8 for hi half)
            uint32_t b0, b1, c0, c1;
            ldsm_x4t(b0, b1, c0, c1,
                     smb + VS0 + (kg * 16 + a_roff) * 144
                               + (ntp * 16 + ((lane & 16) ? 8 : 0)) * 2);
            mma_f16(o[2*ntp],     a0, a1, a2, a3, b0, b1);
            mma_f16(o[2*ntp + 1], a0, a1, a2, a3, c0, c1);
        }
    }

    // ---- normalize + store half ----
    const float inv0 = 1.f / s0;
    const float inv1 = 1.f / s1;
    #pragma unroll
    for (int nt = 0; nt < 8; nt++) {
        int col = h * 64 + nt * 8 + gc * 2;
        *(__half2*)(out + (size_t)(p * 128 + i0) * C_DIM + col) =
            __floats2half2_rn(o[nt][0] * inv0, o[nt][1] * inv0);
        *(__half2*)(out + (size_t)(p * 128 + i1) * C_DIM + col) =
            __floats2half2_rn(o[nt][2] * inv1, o[nt][3] * inv1);
    }
}

// ---------------------------------------------------------------------------
extern "C" void kernel_launch(void* const* d_in, const int* in_sizes, int n_in,
                              void* d_out, int out_size)
{
    const float* feat   = (const float*)d_in[0];
    const int*   gcoord = (const int*)  d_in[1];
    const int*   order  = (const int*)  d_in[2];
    const float* qkv_w  = (const float*)d_in[4];
    const float* qkv_b  = (const float*)d_in[5];
    const float* proj_w = (const float*)d_in[6];
    const float* proj_b = (const float*)d_in[7];
    const float* rpe    = (const float*)d_in[8];
    float* out = (float*)d_out;

    int rpe_num = in_sizes[8] / (3 * H_NUM);   // 31 (ref comment is wrong)
    if (rpe_num > RPE_MAX) rpe_num = RPE_MAX;
    int pos_b = (rpe_num - 1) / 2;

    __half *qkv_buf = nullptr, *ao_buf = nullptr, *gath = nullptr,
           *w1 = nullptr, *w3 = nullptr;
    cudaGetSymbolAddress((void**)&qkv_buf, g_qkv);
    cudaGetSymbolAddress((void**)&ao_buf,  g_ao);
    cudaGetSymbolAddress((void**)&gath,    g_gath);
    cudaGetSymbolAddress((void**)&w1,      g_w1);
    cudaGetSymbolAddress((void**)&w3,      g_w3);

    cudaFuncSetAttribute(gemm_h<1>,
                         cudaFuncAttributeMaxDynamicSharedMemorySize, DYN_SMEM);
    cudaFuncSetAttribute(gemm_h<0>,
                         cudaFuncAttributeMaxDynamicSharedMemorySize, DYN_SMEM);
    cudaFuncSetAttribute(attn_kernel,
                         cudaFuncAttributeMaxDynamicSharedMemorySize, ATTN_SMEM);

    // Pre-pass: gather+cvt feat, cvt weights (all to fp16)
    gather_cvt<<<(N_TOT * (C_DIM / 8)) / 256, 256>>>(feat, order, gath);
    cvt_half<<<(C3 * C_DIM / 8) / 256, 256>>>(qkv_w, w1);
    cvt_half<<<(C_DIM * C_DIM / 8) / 256, 256>>>(proj_w, w3);

    // Stage 1: QKV projection (fp16 in, half out)
    dim3 g1(C3 / 128, N_TOT / 256);
    gemm_h<1><<<g1, 512, DYN_SMEM>>>(gath, w1, qkv_b, qkv_buf, nullptr,
                                     C3, C_DIM);

    // Stage 2: attention (half in, half out)
    dim3 ga(P_NUM, H_NUM);
    attn_kernel<<<ga, 256, ATTN_SMEM>>>(qkv_buf, gcoord, order, rpe,
                                        ao_buf, rpe_num, pos_b);

    // Stage 3: output projection + scatter (half in, fp32 out)
    dim3 g3(C_DIM / 128, N_TOT / 256);
    gemm_h<0><<<g3, 512, DYN_SMEM>>>(ao_buf, w3, proj_b, out, order,
                                     C_DIM, C_DIM);
}